// round 12
// baseline (speedup 1.0000x reference)
#include <cuda_runtime.h>
#include <cstdint>
#include <math.h>

// ---------------------------------------------------------------------------
// ClassicalMappedQRNN fast path (alpha=beta=pi/2). B=8192 chains, S=4096.
// WARP-SPECIALIZED: block = 128 threads = 4 warps on 4 SMSPs.
//   warps 0,1 : serial recurrence, 32 chains each (1 chain/thread)
//   warps 2,3 : trig producers for warps 0,1 resp. (same chains)
// Producer streams per step float4 (C, S, c, -):
//   C = sqrt2*cos(phi/2) = sqrt(1+r),  S = sqrt2*sin(phi/2) = x r/sqrt(1+r),
//   r = rsqrt(1+x^2),  c_t = 2(C_{t-1}C_t + S_{t-1}S_t)      [input-only]
// Serial recurrence (G, K = sqrt2/||G||, v=(C,-S,S,C), ||v||=2):
//   d_t = c_t - 2K_{t-2} (C_t gm + S_t bt),  gm,bt = butterflies of G_{t-2}
//   m_t = 4 + K_{t-1} d_t;   K_t = rsqrt(m_t)
//   G_t = K_{t-1} W(G_{t-1}) + v_t
// PIPELINED ITERATION (fixes the stall-bound serial warp):
//   m is loop-carried: iteration t does  K_t = rsq(m_t)  FIRST, then ~13
//   independent instrs (state update needs only K_{t-1}; up/z for t+1 needs
//   only queues from t-1 and f_{t+1}), then m_{t+1} = fma(K_t, z, 4) — the
//   16-cyc rsq latency is buried under useful work instead of exposed.
//   f is LDS-loaded TWO iterations ahead (consumed mid-iteration).
// ---------------------------------------------------------------------------

#define CHUNK  16
#define TPB    128
#define GUARD4 4.000021f

__device__ __forceinline__ float rsqa(float x) {
    float y; asm("rsqrt.approx.f32 %0, %1;" : "=f"(y) : "f"(x)); return y;
}
__device__ __forceinline__ void barp(int id) {
    asm volatile("bar.sync %0, 64;" :: "r"(id) : "memory");
}

// [pair(2)][buf(2)][t(16)][lane(32)] float4 = 32768 bytes (static)
__shared__ float4 sb4[2 * 2 * CHUNK * 32];

// ---------------- serial side ----------------
struct SState {
    float g0, g1, g2, g3, K;
    float qg[2], qb[2], qK2[2];   // butterflies + doubled K from step t-2
};

// One pipelined iteration. fc = f_t (state update), fn = f_{t+1} (up/z).
// m enters as m_t, leaves as m_{t+1} (unless LAST).
template <bool LAST>
__device__ __forceinline__ void s_iter(SState& s, float4 fc, float4 fn,
                                       int par, float& m) {
    float Kn = rsqa(m);                                // K_t (16-cyc latency)
    // --- state update: uses K_{t-1} only (independent of Kn) ---
    float w0 = s.g0 - s.g1, w1 = s.g0 + s.g1;
    float w2 = s.g2 + s.g3, w3 = s.g3 - s.g2;
    float n0 = fmaf(s.K, w0,  fc.x);
    float n1 = fmaf(s.K, w1, -fc.y);
    float n2 = fmaf(s.K, w2,  fc.y);
    float n3 = fmaf(s.K, w3,  fc.x);
    s.qg[par] = n1 + n2;
    s.qb[par] = n0 - n3;
    if (!LAST) {
        // --- front half of step t+1: queues from t-1, f_{t+1} ---
        int pn = par ^ 1;
        float up = fmaf(fn.y, s.qb[pn], fn.x * s.qg[pn]);
        float z  = fmaf(-s.qK2[pn], up, fn.z);         // d_{t+1}
        m = fmaf(Kn, z, GUARD4);                       // first consumer of Kn
    }
    s.qK2[par] = Kn + Kn;
    s.g0 = n0; s.g1 = n1; s.g2 = n2; s.g3 = n3;
    s.K = Kn;
}

template <bool FIRST>
__device__ __forceinline__ void consume_chunk(SState& s, const float4* sb) {
    float m;
    float4 fc, fn, fnn;
    if (FIRST) {
        float4 f0 = sb[0];
        s.g0 = f0.x; s.g1 = -f0.y; s.g2 = f0.y; s.g3 = f0.x;  // G0 = v0
        s.K = 0.70710678118654752f;
        s.qg[0] = 0.0f; s.qb[0] = 0.0f;                // butterflies(G0) = 0
        s.qK2[0] = 1.41421356237309505f;
        fc = sb[32];                                   // f_1
        fn = sb[64];                                   // f_2
        // direct m_1 (no G_{-1} for the decomposition)
        float w0 = s.g0 - s.g1, w1 = s.g0 + s.g1;
        float w2 = s.g2 + s.g3, w3 = s.g3 - s.g2;
        float d = fmaf(fc.y, w2 - w1, fc.x * (w0 + w3));
        m = fmaf(s.K, d, GUARD4);
        #pragma unroll
        for (int t = 1; t < CHUNK; t++) {
            fnn = (t + 2 < CHUNK) ? sb[(t + 2) * 32] : fc;   // load 2 ahead
            if (t + 1 < CHUNK) s_iter<false>(s, fc, fn, t & 1, m);
            else               s_iter<true >(s, fc, fn, t & 1, m);
            fc = fn; fn = fnn;
        }
    } else {
        fc = sb[0];                                    // f_0 of this chunk
        fn = sb[32];                                   // f_1
        // prologue: m for local t=0 (queues from prev chunk's t=14; par 0)
        float up = fmaf(fc.y, s.qb[0], fc.x * s.qg[0]);
        float z  = fmaf(-s.qK2[0], up, fc.z);
        m = fmaf(s.K, z, GUARD4);
        #pragma unroll
        for (int t = 0; t < CHUNK; t++) {
            fnn = (t + 2 < CHUNK) ? sb[(t + 2) * 32] : fc;   // load 2 ahead
            if (t + 1 < CHUNK) s_iter<false>(s, fc, fn, t & 1, m);
            else               s_iter<true >(s, fc, fn, t & 1, m);
            fc = fn; fn = fnn;
        }
    }
    // exact renorm every CHUNK steps: kills approx-rsqrt drift
    float ss = (s.g0 * s.g0 + s.g1 * s.g1) + (s.g2 * s.g2 + s.g3 * s.g3);
    s.K = rsqa(0.5f * ss);
}

// ---------------- producer side ----------------
struct PReg { float4 a[CHUNK / 4]; };

__device__ __forceinline__ void p_load(PReg& r, const float* __restrict__ xrow,
                                       int c) {
    const float4* p = reinterpret_cast<const float4*>(xrow + c * CHUNK);
    #pragma unroll
    for (int i = 0; i < CHUNK / 4; i++) r.a[i] = __ldg(p + i);
}

__device__ __forceinline__ void p_emit(float x, float& Cp, float& Sp,
                                       float4* dst) {
    float tq = fmaf(x, x, 1.0f);
    float r  = rsqa(tq);
    float e  = r + 1.0f;
    float q  = rsqa(e);
    float C  = e * q;                      // sqrt2 cos(phi/2)
    float S  = (x * r) * q;                // sqrt2 sin(phi/2)
    float cc = fmaf(S, Sp, C * Cp);
    float c2 = cc + cc;                    // 2(CC'+SS')
    *dst = make_float4(C, S, c2, 0.0f);
    Cp = C; Sp = S;
}

__device__ __forceinline__ void p_chunk(const PReg& r, float& Cp, float& Sp,
                                        float4* wb) {
    #pragma unroll
    for (int i = 0; i < CHUNK / 4; i++) {
        p_emit(r.a[i].x, Cp, Sp, wb + (i * 4 + 0) * 32);
        p_emit(r.a[i].y, Cp, Sp, wb + (i * 4 + 1) * 32);
        p_emit(r.a[i].z, Cp, Sp, wb + (i * 4 + 2) * 32);
        p_emit(r.a[i].w, Cp, Sp, wb + (i * 4 + 3) * 32);
    }
}

// ---------------- fallback ----------------
__device__ void run_simple(const float* __restrict__ xrow, float* __restrict__ outb,
                           int S, float ca, float sa, float cb, float sb) {
    float h0 = 0.f, h1 = 0.f, h2 = 0.f, h3 = 0.f;
    for (int t = 0; t < S; t++) {
        float xv = xrow[t];
        float phi = atanf(xv);
        float c = cosf(0.5f * phi);
        float s = sinf(0.5f * phi);
        float u0 = ca * c + cb * h0 - sb * h1;
        float u1 = -(sa * s) + sb * h0 + cb * h1;
        float u2 = ca * s + cb * h2 + sb * h3;
        float u3 = sa * c - sb * h2 + cb * h3;
        float ss = u0*u0 + u1*u1 + u2*u2 + u3*u3;
        float rn = rsqrtf(ss);
        h0 = u0 * rn; h1 = u1 * rn; h2 = u2 * rn; h3 = u3 * rn;
    }
    *outb = (h0*h0 + h1*h1) - (h2*h2 + h3*h3);
}

// ---------------- kernel ----------------
__global__ void __launch_bounds__(TPB, 1)
qrnn_kernel(const float* __restrict__ x, const float* __restrict__ pa,
            const float* __restrict__ pb, float* __restrict__ out, int B, int S) {
    int tid  = threadIdx.x;
    int wid  = tid >> 5;
    int lane = tid & 31;

    float alpha = __ldg(pa);
    float beta  = __ldg(pb);
    const float PIO2 = 1.57079632679489662f;
    bool fast = (fabsf(alpha - PIO2) < 1e-5f) && (fabsf(beta - PIO2) < 1e-5f)
                && (S % 64 == 0) && (S >= 128);

    if (!fast) {
        if (tid < 64) {
            int b = blockIdx.x * 64 + tid;
            if (b < B) {
                float ca = cosf(0.5f * alpha), sa = sinf(0.5f * alpha);
                float cb = cosf(0.5f * beta),  sb = sinf(0.5f * beta);
                run_simple(x + (size_t)b * S, out + b, S, ca, sa, cb, sb);
            }
        }
        return;
    }

    const int nch = S / CHUNK;        // multiple of 4 (S % 64 == 0)

    if (wid < 2) {
        // ------------- serial role -------------
        int w  = wid;
        int b  = blockIdx.x * 64 + w * 32 + lane;
        int id = 1 + w;
        const float4* rb0 = sb4 + (w * 2 + 0) * (CHUNK * 32) + lane;
        const float4* rb1 = sb4 + (w * 2 + 1) * (CHUNK * 32) + lane;

        SState s;
        barp(id);                                  // wait: chunk 0 ready
        #pragma unroll 1
        for (int c = 0; c < nch; c++) {
            if (c == 0) consume_chunk<true >(s, rb0);
            else        consume_chunk<false>(s, (c & 1) ? rb1 : rb0);
            barp(id);
        }

        if (b < B) {
            float a01 = s.g0 * s.g0 + s.g1 * s.g1;
            float a23 = s.g2 * s.g2 + s.g3 * s.g3;
            out[b] = (a01 - a23) / (a01 + a23);
        }
    } else {
        // ------------- producer role -------------
        int w  = wid - 2;
        int b  = blockIdx.x * 64 + w * 32 + lane;
        if (b >= B) b = B - 1;                     // clamp (keeps bars uniform)
        int id = 1 + w;
        const float* xrow = x + (size_t)b * S;
        float4* wb0 = sb4 + (w * 2 + 0) * (CHUNK * 32) + lane;
        float4* wb1 = sb4 + (w * 2 + 1) * (CHUNK * 32) + lane;

        float Cp = 0.0f, Sp = 0.0f;
        PReg ra, rbuf;
        p_load(ra, xrow, 0);

        #pragma unroll 1
        for (int c = 0; c < nch; c += 2) {
            int c1 = (c + 1 < nch) ? c + 1 : c;
            p_load(rbuf, xrow, c1);
            p_chunk(ra, Cp, Sp, wb0);              // chunk c   -> buf 0
            barp(id);
            int c2 = (c + 2 < nch) ? c + 2 : c1;
            p_load(ra, xrow, c2);
            p_chunk(rbuf, Cp, Sp, wb1);            // chunk c+1 -> buf 1
            barp(id);
        }
        barp(id);                                  // match serial's final wait
    }
}

extern "C" void kernel_launch(void* const* d_in, const int* in_sizes, int n_in,
                              void* d_out, int out_size) {
    const float* x  = (const float*)d_in[0];
    const float* pa = (const float*)d_in[1];
    const float* pb = (const float*)d_in[2];
    float* out = (float*)d_out;

    int B = out_size;                 // 8192
    int S = in_sizes[0] / B;          // 4096

    int grid = (B + 63) / 64;         // 128 blocks x 128 threads, 1 block/SM
    qrnn_kernel<<<grid, TPB>>>(x, pa, pb, out, B, S);
}